// round 4
// baseline (speedup 1.0000x reference)
#include <cuda_runtime.h>
#include <cuda_bf16.h>
#include <cfloat>
#include <math.h>

// Problem constants (shapes fixed by the dataset: B=512, F=512, depth=8)
#define BB 512        // batch
#define FF 512        // features
#define NS 255        // n_splits = 2^8 - 1
#define NN 511        // n_nodes  = 2^9 - 1
#define NC 21         // N_CAND
#define TEMP 100.0f

// Scratch (no cudaMalloc allowed)
__device__ float g_qsplit[BB * NS];
__device__ float g_qnode[BB * NN];
__device__ float g_ga[NN * NC];
__device__ float g_anode[NN];

// ---------------------------------------------------------------------------
// Kernel 1: q_split = x @ W + b   (512x512 @ 512x255)
// 32x32 tiles, 16x16 threads, 2x2 micro-tile.
// ---------------------------------------------------------------------------
__global__ void gemm_kernel(const float* __restrict__ x,
                            const float* __restrict__ W,
                            const float* __restrict__ bias,
                            float* __restrict__ q) {
    __shared__ float As[32][33];
    __shared__ float Bs[32][33];
    int tx = threadIdx.x, ty = threadIdx.y;          // 16 x 16
    int row0 = blockIdx.y * 32, col0 = blockIdx.x * 32;
    int lin = ty * 16 + tx;                          // 0..255
    int lr = lin >> 5, lc = lin & 31;

    float c00 = 0.f, c01 = 0.f, c10 = 0.f, c11 = 0.f;

    for (int k0 = 0; k0 < FF; k0 += 32) {
#pragma unroll
        for (int i = 0; i < 4; i++) {
            int r = lr + i * 8;
            As[r][lc] = x[(row0 + r) * FF + k0 + lc];
            int wc = col0 + lc;
            Bs[r][lc] = (wc < NS) ? W[(k0 + r) * NS + wc] : 0.0f;
        }
        __syncthreads();
#pragma unroll
        for (int kk = 0; kk < 32; kk++) {
            float a0 = As[ty][kk], a1 = As[ty + 16][kk];
            float b0 = Bs[kk][tx], b1 = Bs[kk][tx + 16];
            c00 += a0 * b0; c01 += a0 * b1;
            c10 += a1 * b0; c11 += a1 * b1;
        }
        __syncthreads();
    }
    int r0 = row0 + ty, r1 = row0 + ty + 16;
    int cA = col0 + tx, cB = col0 + tx + 16;
    if (cA < NS) {
        float bv = bias[cA];
        q[r0 * NS + cA] = c00 + bv;
        q[r1 * NS + cA] = c10 + bv;
    }
    if (cB < NS) {
        float bv = bias[cB];
        q[r0 * NS + cB] = c01 + bv;
        q[r1 * NS + cB] = c11 + bv;
    }
}

// ---------------------------------------------------------------------------
// Kernel 2: q_node[b,n] = min(1, min over ancestor splits of +/- q_split)
// One block per batch row; each thread walks its node's ancestor chain (<=8).
// ---------------------------------------------------------------------------
__global__ void qnode_kernel(const float* __restrict__ q,
                             float* __restrict__ qn) {
    __shared__ float sq[NS];
    int b = blockIdx.x;
    int t = threadIdx.x;
    if (t < NS) sq[t] = q[b * NS + t];
    __syncthreads();
    if (t < NN) {
        float v = 1.0f;
        int a = t;
        while (a > 0) {
            int p = (a - 1) >> 1;
            float s = sq[p];
            v = fminf(v, (a & 1) ? -s : s);   // left child (odd) -> -1 sign
            a = p;
        }
        qn[b * NN + t] = v;
    }
}

// ---------------------------------------------------------------------------
// Kernel 3: g_a[n,c] = 0.5*a_c^2 + 0.5 * sum_b [a_c <= q+0.5] (a_c-(q+0.5))^2
// One block per node, deterministic shared-memory tree reduction over batch.
// ---------------------------------------------------------------------------
__global__ void ga_kernel(const float* __restrict__ qn,
                          float* __restrict__ ga) {
    int n = blockIdx.x;
    int t = threadIdx.x;            // 256 threads
    float acc[NC];
#pragma unroll
    for (int c = 0; c < NC; c++) acc[c] = 0.0f;

    for (int b = t; b < BB; b += 256) {
        float thr = qn[b * NN + n] + 0.5f;
#pragma unroll
        for (int c = 0; c < NC; c++) {
            float ac = (float)c * 0.05f;
            float d = ac - thr;
            if (ac <= thr) acc[c] += d * d;
        }
    }
    __shared__ float red[NC][256];
#pragma unroll
    for (int c = 0; c < NC; c++) red[c][t] = acc[c];
    __syncthreads();
    for (int s = 128; s > 0; s >>= 1) {
        if (t < s) {
#pragma unroll
            for (int c = 0; c < NC; c++) red[c][t] += red[c][t + s];
        }
        __syncthreads();
    }
    if (t < NC) {
        float ac = (float)t * 0.05f;
        ga[n * NC + t] = 0.5f * ac * ac + 0.5f * red[t][0];
    }
}

// ---------------------------------------------------------------------------
// Kernel 4: the sequential merge scan. Single block, 512 threads.
// State = cnt[i] (times node i was merged into its parent group).
//   g_grp[g] = (1-cnt[g])*g_a[g] + cnt[l]*g_a[l] + cnt[r]*g_a[r]
//   a_node[i] = cnt[i]*a_grp[par(i)] + (1-cnt[i])*a_grp[i]
// Only groups {t, par(t)} change per iteration -> warp-parallel softmax update.
// Early exit: cond==false is a fixed point.
// ---------------------------------------------------------------------------
__device__ __forceinline__ void agrp_update(int g, int lane,
                                            const float* __restrict__ ga,
                                            const int* s_cnt,
                                            float* s_agrp) {
    float z = -FLT_MAX;
    if (lane < NC) {
        float gg = (1.0f - (float)s_cnt[g]) * __ldg(&ga[g * NC + lane]);
        int l = 2 * g + 1, r = 2 * g + 2;
        if (l < NN) gg += (float)s_cnt[l] * __ldg(&ga[l * NC + lane]);
        if (r < NN) gg += (float)s_cnt[r] * __ldg(&ga[r * NC + lane]);
        z = -TEMP * gg;
    }
    // warp max
    float m = z;
#pragma unroll
    for (int off = 16; off; off >>= 1)
        m = fmaxf(m, __shfl_xor_sync(0xffffffffu, m, off));
    float e = (lane < NC) ? expf(z - m) : 0.0f;
    float s = e;
#pragma unroll
    for (int off = 16; off; off >>= 1)
        s += __shfl_xor_sync(0xffffffffu, s, off);
    float aw = (lane < NC) ? ((float)lane * 0.05f) * (e / s) : 0.0f;
#pragma unroll
    for (int off = 16; off; off >>= 1)
        aw += __shfl_xor_sync(0xffffffffu, aw, off);
    if (lane == 0) s_agrp[g] = aw;
}

__global__ void scan_kernel(const float* __restrict__ ga,
                            float* __restrict__ anode_out) {
    __shared__ float s_agrp[NN + 1];
    __shared__ float s_anode[NN + 1];
    __shared__ int   s_cnt[NN + 1];
    __shared__ float s_rv[16];
    __shared__ int   s_ri[16];
    __shared__ int   s_t;
    __shared__ int   s_stop;

    int tid = threadIdx.x;            // 512
    int lane = tid & 31;
    int w = tid >> 5;                 // 16 warps

    s_cnt[tid] = 0;
    __syncthreads();

    // Initial a_grp for all 511 groups (cnt==0)
    for (int g = w; g < NN; g += 16)
        agrp_update(g, lane, ga, s_cnt, s_agrp);
    __syncthreads();

    for (int iter = 0; iter < NN + 1; ++iter) {
        // a_node
        if (tid < NN) {
            float fc = (float)s_cnt[tid];
            float an = (tid == 0)
                ? s_agrp[0]
                : fc * s_agrp[(tid - 1) >> 1] + (1.0f - fc) * s_agrp[tid];
            s_anode[tid] = an;
        }
        __syncthreads();

        // violations + first-occurrence argmax
        float v = -FLT_MAX;
        int idx = tid;
        if (tid == 0)       v = s_anode[0] - 1.0f;
        else if (tid < NN)  v = s_anode[tid] - s_anode[(tid - 1) >> 1];
#pragma unroll
        for (int off = 16; off; off >>= 1) {
            float ov = __shfl_down_sync(0xffffffffu, v, off);
            int   oi = __shfl_down_sync(0xffffffffu, idx, off);
            if (ov > v || (ov == v && oi < idx)) { v = ov; idx = oi; }
        }
        if (lane == 0) { s_rv[w] = v; s_ri[w] = idx; }
        __syncthreads();
        if (tid == 0) {
            float bv = s_rv[0]; int bi = s_ri[0];
#pragma unroll
            for (int i = 1; i < 16; i++) {
                if (s_rv[i] > bv || (s_rv[i] == bv && s_ri[i] < bi)) {
                    bv = s_rv[i]; bi = s_ri[i];
                }
            }
            if (bv <= 1e-8f && bi > 0 && iter < NN) {
                s_cnt[bi]++;            // apply merge
                s_t = bi;
                s_stop = 0;
            } else {
                s_stop = 1;             // fixed point (or last body): a_node final
            }
        }
        __syncthreads();
        if (s_stop) break;

        int t = s_t, p = (t - 1) >> 1;
        if (w == 0)      agrp_update(t, lane, ga, s_cnt, s_agrp);
        else if (w == 1) agrp_update(p, lane, ga, s_cnt, s_agrp);
        __syncthreads();
    }

    if (tid < NN) anode_out[tid] = s_anode[tid];
}

// ---------------------------------------------------------------------------
// Kernel 5: trajectory = clip(q_node, 0, a_node)
// ---------------------------------------------------------------------------
__global__ void out_kernel(const float* __restrict__ qn,
                           const float* __restrict__ an,
                           float* __restrict__ out) {
    int i = blockIdx.x * blockDim.x + threadIdx.x;
    if (i < BB * NN) {
        int n = i % NN;
        out[i] = fminf(fmaxf(qn[i], 0.0f), __ldg(&an[n]));
    }
}

// ---------------------------------------------------------------------------
extern "C" void kernel_launch(void* const* d_in, const int* in_sizes, int n_in,
                              void* d_out, int out_size) {
    const float* x = (const float*)d_in[0];
    const float* W = (const float*)d_in[1];
    const float* b = (const float*)d_in[2];
    // d_in[3] = max_depth (compile-time constant here)
    float* out = (float*)d_out;

    float* qsplit;  cudaGetSymbolAddress((void**)&qsplit, g_qsplit);
    float* qnode;   cudaGetSymbolAddress((void**)&qnode,  g_qnode);
    float* ga;      cudaGetSymbolAddress((void**)&ga,     g_ga);
    float* anode;   cudaGetSymbolAddress((void**)&anode,  g_anode);

    dim3 gblk(16, 16);
    dim3 ggrd((NS + 31) / 32, BB / 32);
    gemm_kernel<<<ggrd, gblk>>>(x, W, b, qsplit);

    qnode_kernel<<<BB, 512>>>(qsplit, qnode);

    ga_kernel<<<NN, 256>>>(qnode, ga);

    scan_kernel<<<1, 512>>>(ga, anode);

    int total = BB * NN;
    out_kernel<<<(total + 255) / 256, 256>>>(qnode, anode, out);
}

// round 5
// speedup vs baseline: 1.1097x; 1.1097x over previous
#include <cuda_runtime.h>
#include <cuda_bf16.h>
#include <cfloat>
#include <math.h>

// Problem constants (fixed: B=512, F=512, depth=8)
#define BB 512        // batch
#define FF 512        // features
#define NS 255        // n_splits = 2^8 - 1
#define NN 511        // n_nodes  = 2^9 - 1
#define NC 21         // N_CAND
#define TEMP 100.0f

// Scratch (no cudaMalloc allowed)
__device__ float g_qsplit[BB * NS];
__device__ float g_qnode[BB * NN];
__device__ float g_ga[NN * NC];
__device__ float g_anode[NN];

// ---------------------------------------------------------------------------
// Kernel 1: q_split = x @ W + b   (512x512 @ 512x255)
// ---------------------------------------------------------------------------
__global__ void gemm_kernel(const float* __restrict__ x,
                            const float* __restrict__ W,
                            const float* __restrict__ bias,
                            float* __restrict__ q) {
    __shared__ float As[32][33];
    __shared__ float Bs[32][33];
    int tx = threadIdx.x, ty = threadIdx.y;          // 16 x 16
    int row0 = blockIdx.y * 32, col0 = blockIdx.x * 32;
    int lin = ty * 16 + tx;                          // 0..255
    int lr = lin >> 5, lc = lin & 31;

    float c00 = 0.f, c01 = 0.f, c10 = 0.f, c11 = 0.f;

    for (int k0 = 0; k0 < FF; k0 += 32) {
#pragma unroll
        for (int i = 0; i < 4; i++) {
            int r = lr + i * 8;
            As[r][lc] = x[(row0 + r) * FF + k0 + lc];
            int wc = col0 + lc;
            Bs[r][lc] = (wc < NS) ? W[(k0 + r) * NS + wc] : 0.0f;
        }
        __syncthreads();
#pragma unroll
        for (int kk = 0; kk < 32; kk++) {
            float a0 = As[ty][kk], a1 = As[ty + 16][kk];
            float b0 = Bs[kk][tx], b1 = Bs[kk][tx + 16];
            c00 += a0 * b0; c01 += a0 * b1;
            c10 += a1 * b0; c11 += a1 * b1;
        }
        __syncthreads();
    }
    int r0 = row0 + ty, r1 = row0 + ty + 16;
    int cA = col0 + tx, cB = col0 + tx + 16;
    if (cA < NS) {
        float bv = bias[cA];
        q[r0 * NS + cA] = c00 + bv;
        q[r1 * NS + cA] = c10 + bv;
    }
    if (cB < NS) {
        float bv = bias[cB];
        q[r0 * NS + cB] = c01 + bv;
        q[r1 * NS + cB] = c11 + bv;
    }
}

// ---------------------------------------------------------------------------
// Kernel 2: q_node[b,n] = min(1, min over ancestor splits of +/- q_split)
// ---------------------------------------------------------------------------
__global__ void qnode_kernel(const float* __restrict__ q,
                             float* __restrict__ qn) {
    __shared__ float sq[NS];
    int b = blockIdx.x;
    int t = threadIdx.x;
    if (t < NS) sq[t] = q[b * NS + t];
    __syncthreads();
    if (t < NN) {
        float v = 1.0f;
        int a = t;
        while (a > 0) {
            int p = (a - 1) >> 1;
            float s = sq[p];
            v = fminf(v, (a & 1) ? -s : s);   // left child (odd) -> -1 sign
            a = p;
        }
        qn[b * NN + t] = v;
    }
}

// ---------------------------------------------------------------------------
// Kernel 3 (coalesced): g_a[n,c] = 0.5*a_c^2 + 0.5*sum_b [a_c<=q+0.5](a_c-(q+0.5))^2
// Block = 32 consecutive nodes; lanes map to nodes -> coalesced qn reads.
// Deterministic ascending 8-way reduction over batch groups.
// ---------------------------------------------------------------------------
__global__ void ga_kernel(const float* __restrict__ qn,
                          float* __restrict__ ga) {
    __shared__ float red[8][32 * NC];       // 21.5 KB
    int lane = threadIdx.x & 31;            // node lane
    int bg   = threadIdx.x >> 5;            // batch group 0..7
    int n = blockIdx.x * 32 + lane;
    bool valid = n < NN;

    float acc[NC];
#pragma unroll
    for (int c = 0; c < NC; c++) acc[c] = 0.f;

    for (int b = bg; b < BB; b += 8) {
        float thr = valid ? (qn[b * NN + n] + 0.5f) : 0.f;
#pragma unroll
        for (int c = 0; c < NC; c++) {
            float a = 0.05f * (float)c;
            float d = a - thr;
            if (a <= thr) acc[c] += d * d;
        }
    }
#pragma unroll
    for (int c = 0; c < NC; c++) red[bg][lane * NC + c] = acc[c];
    __syncthreads();

    for (int o = threadIdx.x; o < 32 * NC; o += 256) {
        float s = 0.f;
#pragma unroll
        for (int g2 = 0; g2 < 8; g2++) s += red[g2][o];
        int ln = o / NC, c = o % NC;
        int nn = blockIdx.x * 32 + ln;
        if (nn < NN) {
            float a = 0.05f * (float)c;
            ga[nn * NC + c] = 0.5f * a * a + 0.5f * s;
        }
    }
}

// ---------------------------------------------------------------------------
// Kernel 4: sequential merge scan.
// Setup (16 warps): ga -> smem, initial softmax per group (materialized exps,
// deterministic serial sums). Loop (warp 0 only, no block barriers):
//   - per-lane first-argmax over viol (recomputed from anode, 16 nodes/lane)
//   - cross-lane argmax via redux on ordered key + first-index tie-break
//   - dual softmax (groups t and par(t)) fused in one warp
//   - incremental anode update (only 5 affected nodes)
// Early exit: cond==false is a fixed point of the reference scan.
// ---------------------------------------------------------------------------
__device__ __forceinline__ unsigned ordk(float x) {
    unsigned b = __float_as_uint(x);
    return (b & 0x80000000u) ? ~b : (b | 0x80000000u);
}
__device__ __forceinline__ float iordk(unsigned k) {
    unsigned b = (k & 0x80000000u) ? (k ^ 0x80000000u) : ~k;
    return __uint_as_float(b);
}

__global__ void scan_kernel(const float* __restrict__ ga,
                            float* __restrict__ anode_out) {
    extern __shared__ float dyn[];
    float* s_ga = dyn;               // NN*NC = 10731 floats
    float* s_e  = dyn + NN * NC;     // 10731 floats (setup scratch)
    __shared__ float s_agrp[512];
    __shared__ float s_anode[512];
    __shared__ float s_mz[512];
    __shared__ int   s_cnt[512];

    int tid = threadIdx.x;           // 512

    // ---- setup (all 16 warps) ----
    for (int i = tid; i < NN * NC; i += 512) s_ga[i] = ga[i];
    s_cnt[tid] = 0;
    if (tid == 511) s_anode[511] = 0.f;   // pad slot (never used as valid)
    __syncthreads();

    if (tid < NN) {                  // per-group max of z = -TEMP*g
        const float* row = s_ga + tid * NC;
        float m = -FLT_MAX;
#pragma unroll
        for (int c = 0; c < NC; c++) m = fmaxf(m, -TEMP * row[c]);
        s_mz[tid] = m;
    }
    __syncthreads();

    for (int i = tid; i < NN * NC; i += 512) {
        int g = i / NC;
        s_e[i] = expf(-TEMP * s_ga[i] - s_mz[g]);
    }
    __syncthreads();

    if (tid < NN) {                  // deterministic ascending sums
        const float* er = s_e + tid * NC;
        float s = 0.f, aw = 0.f;
#pragma unroll
        for (int c = 0; c < NC; c++) { float e = er[c]; s += e; aw += (0.05f * (float)c) * e; }
        float a = aw / s;
        s_agrp[tid] = a;
        s_anode[tid] = a;            // n2g = I initially
    }
    __syncthreads();

    if (tid >= 32) return;           // warp 0 runs the loop alone

    int lane = tid;
    const unsigned FULL = 0xffffffffu;
    int  cl = (lane < NC) ? lane : (NC - 1);   // clamped candidate index
    float ac = 0.05f * (float)cl;

    for (int iter = 0; iter <= NN; ++iter) {
        // ---- violations + per-lane first-argmax (strided ownership) ----
        float bv = -FLT_MAX; int bidx = 0;
#pragma unroll
        for (int k = 0; k < 16; ++k) {
            int i = lane + (k << 5);
            float an = s_anode[i & 511];
            float v = (i == 0) ? (an - 1.0f) : (an - s_anode[(i - 1) >> 1]);
            if (i < NN && v > bv) { bv = v; bidx = i; }
        }
        unsigned key  = ordk(bv);
        unsigned kmax = __reduce_max_sync(FULL, key);
        unsigned match = __ballot_sync(FULL, key == kmax);
        int bml = 0;
        if (key == kmax) bml = __reduce_min_sync(match, bidx);
        int src = __ffs(match) - 1;
        int t = __shfl_sync(FULL, bml, src);
        float vmax = iordk(kmax);

        if (!(vmax <= 1e-8f && t > 0 && iter < NN)) break;

        int p = (t - 1) >> 1;
        if (lane == 0) s_cnt[t] += 1;
        __syncwarp(FULL);

        // ---- dual softmax: groups t and p ----
        int l1 = 2 * t + 1, r1 = 2 * t + 2;
        int l2 = 2 * p + 1, r2 = 2 * p + 2;           // always < NN
        float g1 = (1.0f - (float)s_cnt[t]) * s_ga[t * NC + cl];
        if (l1 < NN) g1 += (float)s_cnt[l1] * s_ga[l1 * NC + cl];
        if (r1 < NN) g1 += (float)s_cnt[r1] * s_ga[r1 * NC + cl];
        float g2 = (1.0f - (float)s_cnt[p]) * s_ga[p * NC + cl]
                 + (float)s_cnt[l2] * s_ga[l2 * NC + cl]
                 + (float)s_cnt[r2] * s_ga[r2 * NC + cl];
        float z1 = -TEMP * g1, z2 = -TEMP * g2;
        unsigned m1 = __reduce_max_sync(FULL, (lane < NC) ? ordk(z1) : 0u);
        unsigned m2 = __reduce_max_sync(FULL, (lane < NC) ? ordk(z2) : 0u);
        float e1 = (lane < NC) ? expf(z1 - iordk(m1)) : 0.f;
        float e2 = (lane < NC) ? expf(z2 - iordk(m2)) : 0.f;
        float s1 = e1, w1 = ac * e1, s2 = e2, w2 = ac * e2;
#pragma unroll
        for (int off = 16; off; off >>= 1) {          // 4 independent butterflies
            s1 += __shfl_xor_sync(FULL, s1, off);
            w1 += __shfl_xor_sync(FULL, w1, off);
            s2 += __shfl_xor_sync(FULL, s2, off);
            w2 += __shfl_xor_sync(FULL, w2, off);
        }
        if (lane == 0) { s_agrp[t] = w1 / s1; s_agrp[p] = w2 / s2; }
        __syncwarp(FULL);

        // ---- incremental anode update: affected = {p, t, sib(t), 2t+1, 2t+2} ----
        if (lane < 5) {
            int i;
            switch (lane) {
                case 0:  i = p; break;
                case 1:  i = t; break;
                case 2:  i = (t & 1) ? (t + 1) : (t - 1); break;
                case 3:  i = l1; break;
                default: i = r1; break;
            }
            if (i < NN) {
                float an;
                if (i == 0) an = s_agrp[0];
                else {
                    float fc = (float)s_cnt[i];
                    an = fc * s_agrp[(i - 1) >> 1] + (1.0f - fc) * s_agrp[i];
                }
                s_anode[i] = an;
            }
        }
        __syncwarp(FULL);
    }

#pragma unroll
    for (int k = 0; k < 16; ++k) {
        int i = lane + (k << 5);
        if (i < NN) anode_out[i] = s_anode[i];
    }
}

// ---------------------------------------------------------------------------
// Kernel 5: trajectory = clip(q_node, 0, a_node)
// ---------------------------------------------------------------------------
__global__ void out_kernel(const float* __restrict__ qn,
                           const float* __restrict__ an,
                           float* __restrict__ out) {
    int i = blockIdx.x * blockDim.x + threadIdx.x;
    if (i < BB * NN) {
        int n = i % NN;
        out[i] = fminf(fmaxf(qn[i], 0.0f), __ldg(&an[n]));
    }
}

// ---------------------------------------------------------------------------
extern "C" void kernel_launch(void* const* d_in, const int* in_sizes, int n_in,
                              void* d_out, int out_size) {
    const float* x = (const float*)d_in[0];
    const float* W = (const float*)d_in[1];
    const float* b = (const float*)d_in[2];
    float* out = (float*)d_out;

    float* qsplit;  cudaGetSymbolAddress((void**)&qsplit, g_qsplit);
    float* qnode;   cudaGetSymbolAddress((void**)&qnode,  g_qnode);
    float* ga;      cudaGetSymbolAddress((void**)&ga,     g_ga);
    float* anode;   cudaGetSymbolAddress((void**)&anode,  g_anode);

    static bool attr_set = false;
    if (!attr_set) {
        cudaFuncSetAttribute(scan_kernel,
                             cudaFuncAttributeMaxDynamicSharedMemorySize,
                             2 * NN * NC * (int)sizeof(float));
        attr_set = true;
    }

    dim3 gblk(16, 16);
    dim3 ggrd((NS + 31) / 32, BB / 32);
    gemm_kernel<<<ggrd, gblk>>>(x, W, b, qsplit);

    qnode_kernel<<<BB, 512>>>(qsplit, qnode);

    ga_kernel<<<(NN + 31) / 32, 256>>>(qnode, ga);

    scan_kernel<<<1, 512, 2 * NN * NC * (int)sizeof(float)>>>(ga, anode);

    int total = BB * NN;
    out_kernel<<<(total + 255) / 256, 256>>>(qnode, anode, out);
}